// round 16
// baseline (speedup 1.0000x reference)
#include <cuda_runtime.h>

// PCEN: smooth[t] = 0.975*smooth[t-1] + 0.025*x[t], smooth[0]=x[0]
//       out = (x / (smooth+1e-6)^0.98 + 2)^0.5 - 2^0.5
//
// Exact warp-cooperative scan. One warp owns one full row (T=4096),
// 32 steps of 128 elements, lane-contiguous float4 I/O (512B/warp request).
// Per step: lane-local Horner fold (decay 0.975^4), 5-round Kogge-Stone
// shuffle scan, 4-smooth reconstruct, PCEN transform, streaming store.
// Cross-step serial chain is ONE FMA (carry' = 0.975^128*carry + p31).
// No SMEM, no barriers, exact.
//
// Single change vs the 49.2us kernel: 4-warp blocks (was 8) -> 2048 blocks
// = 13.8 blocks/SM, recovering the block-granularity occupancy loss
// (47.5 -> ~54 warps/SM) in the one regime this kernel responds to.

namespace {

constexpr int T_LEN = 4096;
constexpr int WPB   = 4;              // warps per block
constexpr int STEP  = 128;            // elements per warp-step
constexpr int NSTEP = T_LEN / STEP;   // 32

constexpr float A1 = 0.975f;
constexpr float S  = 0.025f;
constexpr float C1  = A1 * A1 * A1 * A1;   // 0.975^4
constexpr float C2  = C1 * C1;             // ^8
constexpr float C4  = C2 * C2;             // ^16
constexpr float C8  = C4 * C4;             // ^32
constexpr float C16 = C8 * C8;             // ^64
constexpr float C32 = C16 * C16;           // ^128

__device__ __forceinline__ float pcen_pt(float xv, float sm) {
    float l = __log2f(sm + 1e-6f);                // MUFU.LG2
    float g = exp2f(-0.98f * l);                  // MUFU.EX2
    float v = fmaf(xv, g, 2.0f);
    return rsqrtf(v) * v - 1.41421356237309515f;  // MUFU.RSQ; v >= 2
}

__global__ __launch_bounds__(WPB * 32)
void pcen_kernel(const float* __restrict__ x, float* __restrict__ out) {
    const int lane = threadIdx.x & 31;
    const int row  = blockIdx.x * WPB + (threadIdx.x >> 5);  // grid exact

    const float4* __restrict__ xr =
        reinterpret_cast<const float4*>(x + (size_t)row * T_LEN) + lane;
    float4* __restrict__ orow =
        reinterpret_cast<float4*>(out + (size_t)row * T_LEN) + lane;

    // Al = C1^lane via binary expansion (compile-time constants)
    float Al = 1.0f;
    if (lane & 1)  Al *= C1;
    if (lane & 2)  Al *= C2;
    if (lane & 4)  Al *= C4;
    if (lane & 8)  Al *= C8;
    if (lane & 16) Al *= C16;

    const unsigned FULL = 0xffffffffu;

    float4 v = xr[0];
    float carry = __shfl_sync(FULL, v.x, 0);   // fixed point: smooth[0] = x[0]

    #pragma unroll 4
    for (int k = 0; k < NSTEP; ++k) {
        float4 vn = v;
        if (k + 1 < NSTEP) vn = xr[(k + 1) * (STEP / 4)];

        // lane-local affine offset: b = S*(A1^3 x0 + A1^2 x1 + A1 x2 + x3)
        float b = fmaf(A1, v.x, v.y);
        b = fmaf(A1, b, v.z);
        b = fmaf(A1, b, v.w);
        b *= S;

        // Kogge-Stone inclusive scan with decay C1 per lane-hop
        float p = b, tt;
        tt = __shfl_up_sync(FULL, p, 1);  if (lane >= 1)  p = fmaf(C1, tt, p);
        tt = __shfl_up_sync(FULL, p, 2);  if (lane >= 2)  p = fmaf(C2, tt, p);
        tt = __shfl_up_sync(FULL, p, 4);  if (lane >= 4)  p = fmaf(C4, tt, p);
        tt = __shfl_up_sync(FULL, p, 8);  if (lane >= 8)  p = fmaf(C8, tt, p);
        tt = __shfl_up_sync(FULL, p, 16); if (lane >= 16) p = fmaf(C16, tt, p);

        float pprev = __shfl_up_sync(FULL, p, 1);
        if (lane == 0) pprev = 0.0f;
        float p31 = __shfl_sync(FULL, p, 31);

        float s_in = fmaf(Al, carry, pprev);   // state entering this lane
        carry = fmaf(C32, carry, p31);         // serial chain: ONE FMA per step

        float sm0 = fmaf(A1, s_in, S * v.x);
        float sm1 = fmaf(A1, sm0,  S * v.y);
        float sm2 = fmaf(A1, sm1,  S * v.z);
        float sm3 = fmaf(A1, sm2,  S * v.w);
        float4 o;
        o.x = pcen_pt(v.x, sm0);
        o.y = pcen_pt(v.y, sm1);
        o.z = pcen_pt(v.z, sm2);
        o.w = pcen_pt(v.w, sm3);
        __stcs(&orow[k * (STEP / 4)], o);

        v = vn;
    }
}

}  // namespace

extern "C" void kernel_launch(void* const* d_in, const int* in_sizes, int n_in,
                              void* d_out, int out_size) {
    const float* x = (const float*)d_in[0];
    float* out = (float*)d_out;
    int nrows = in_sizes[0] / T_LEN;            // 8192 warps, one per row
    int blocks = nrows / WPB;                   // 2048 blocks (exact)
    pcen_kernel<<<blocks, WPB * 32>>>(x, out);
}